// round 1
// baseline (speedup 1.0000x reference)
#include <cuda_runtime.h>
#include <math.h>

#define N_ROWS 16384
#define DIM    1024
#define HIDDEN 4096
// IN_DIM = 4*DIM + 1 = 4097; the "+1" (bilinear scalar) is handled as a rank-1 update.

// Scratch (static device globals — allocation-free per harness rules)
__device__ float g_t [(size_t)N_ROWS * DIM];      // zA @ bilinear            64 MB
__device__ float g_xn[(size_t)N_ROWS * HIDDEN];   // normalized x, 4096 cols 256 MB
__device__ float g_sn[N_ROWS];                    // normalized s column
__device__ float g_h [(size_t)N_ROWS * HIDDEN];   // hidden activations      256 MB

__device__ __forceinline__ float gelu_exact(float x) {
    return 0.5f * x * (1.0f + erff(x * 0.70710678118654752440f));
}

// ---------------------------------------------------------------------------
// Tiled fp32 SGEMM: C[M,Ncols] = A[M,K] @ B[K,Ncols] (+ epilogue)
// BM=BN=128, BK=16, 256 threads, 8x8 register tile per thread.
// MODE 0: plain store
// MODE 1: +svec[row]*w_last[col] + bias[col], GELU
// MODE 2: +bias[col], GELU
// Requires: M%128==0, Ncols%128==0, K%16==0 (all true here).
// ---------------------------------------------------------------------------
template <int MODE>
__global__ __launch_bounds__(256, 2)
void sgemm_kernel(const float* __restrict__ A, const float* __restrict__ B,
                  float* __restrict__ C, int M, int Ncols, int K,
                  const float* __restrict__ bias,
                  const float* __restrict__ w_last,
                  const float* __restrict__ svec)
{
    constexpr int BM = 128, BN = 128, BK = 16;
    __shared__ float As[BK][BM];   // transposed A tile
    __shared__ float Bs[BK][BN];

    const int tid = threadIdx.x;
    const int tx  = tid & 15;      // 0..15 -> output col group
    const int ty  = tid >> 4;      // 0..15 -> output row group

    const int row0 = blockIdx.y * BM;
    const int col0 = blockIdx.x * BN;

    // A tile: 128 rows x 16 cols = 512 float4; 2 per thread
    const int a_r  = tid >> 2;           // 0..63
    const int a_c4 = (tid & 3) << 2;     // 0,4,8,12
    // B tile: 16 rows x 128 cols = 512 float4; 2 per thread
    const int b_r  = tid >> 5;           // 0..7
    const int b_c4 = (tid & 31) << 2;    // 0..124 step 4

    const float* Ag = A + (size_t)row0 * K;
    const float* Bg = B + col0;

    float acc[8][8];
    #pragma unroll
    for (int i = 0; i < 8; i++)
        #pragma unroll
        for (int j = 0; j < 8; j++) acc[i][j] = 0.0f;

    for (int k0 = 0; k0 < K; k0 += BK) {
        float4 av0 = *(const float4*)(Ag + (size_t)(a_r)      * K + k0 + a_c4);
        float4 av1 = *(const float4*)(Ag + (size_t)(a_r + 64) * K + k0 + a_c4);
        float4 bv0 = *(const float4*)(Bg + (size_t)(k0 + b_r)     * Ncols + b_c4);
        float4 bv1 = *(const float4*)(Bg + (size_t)(k0 + b_r + 8) * Ncols + b_c4);

        __syncthreads();   // previous tile fully consumed before overwrite

        As[a_c4 + 0][a_r] = av0.x;  As[a_c4 + 1][a_r] = av0.y;
        As[a_c4 + 2][a_r] = av0.z;  As[a_c4 + 3][a_r] = av0.w;
        As[a_c4 + 0][a_r + 64] = av1.x;  As[a_c4 + 1][a_r + 64] = av1.y;
        As[a_c4 + 2][a_r + 64] = av1.z;  As[a_c4 + 3][a_r + 64] = av1.w;
        *(float4*)&Bs[b_r][b_c4]     = bv0;
        *(float4*)&Bs[b_r + 8][b_c4] = bv1;

        __syncthreads();

        #pragma unroll
        for (int k = 0; k < BK; k++) {
            float4 a0 = *(const float4*)&As[k][ty * 8];
            float4 a1 = *(const float4*)&As[k][ty * 8 + 4];
            float4 b0 = *(const float4*)&Bs[k][tx * 8];
            float4 b1 = *(const float4*)&Bs[k][tx * 8 + 4];
            float ra[8] = {a0.x, a0.y, a0.z, a0.w, a1.x, a1.y, a1.z, a1.w};
            float rb[8] = {b0.x, b0.y, b0.z, b0.w, b1.x, b1.y, b1.z, b1.w};
            #pragma unroll
            for (int i = 0; i < 8; i++)
                #pragma unroll
                for (int j = 0; j < 8; j++)
                    acc[i][j] = fmaf(ra[i], rb[j], acc[i][j]);
        }
    }

    // epilogue
    #pragma unroll
    for (int i = 0; i < 8; i++) {
        const int r = row0 + ty * 8 + i;
        float s = 0.0f;
        if (MODE == 1) s = svec[r];
        float* Cr = C + (size_t)r * Ncols + col0 + tx * 8;
        #pragma unroll
        for (int j = 0; j < 8; j++) {
            const int c = col0 + tx * 8 + j;
            float v = acc[i][j];
            if (MODE == 1) v += s * w_last[c] + bias[c];
            if (MODE == 2) v += bias[c];
            if (MODE >= 1) v = gelu_exact(v);
            Cr[j] = v;
        }
    }
}

// ---------------------------------------------------------------------------
// Per-row fusion: s = dot(t_row, zB_row); LayerNorm stats over 4097 virtual
// features [zA, zB, zA*zB, |zA-zB|, s]; write normalized x (4096 cols) and
// normalized s. One block (256 threads) per row; 4 columns per thread.
// ---------------------------------------------------------------------------
__global__ __launch_bounds__(256)
void row_fuse_kernel(const float* __restrict__ zA, const float* __restrict__ zB,
                     const float* __restrict__ t,
                     const float* __restrict__ ln_g, const float* __restrict__ ln_b,
                     float* __restrict__ xn, float* __restrict__ sn)
{
    const int n = blockIdx.x;
    const float* a  = zA + (size_t)n * DIM;
    const float* b  = zB + (size_t)n * DIM;
    const float* tt = t  + (size_t)n * DIM;

    float va[4], vb[4], vh[4], vd[4];
    float sp = 0.0f, sum = 0.0f, sq = 0.0f;

    #pragma unroll
    for (int i = 0; i < 4; i++) {
        const int c = threadIdx.x + i * 256;
        float x1 = a[c], x2 = b[c];
        float hd = x1 * x2;
        float df = fabsf(x1 - x2);
        va[i] = x1; vb[i] = x2; vh[i] = hd; vd[i] = df;
        sp  = fmaf(tt[c], x2, sp);
        sum += x1 + x2 + hd + df;
        sq  = fmaf(x1, x1, sq); sq = fmaf(x2, x2, sq);
        sq  = fmaf(hd, hd, sq); sq = fmaf(df, df, sq);
    }

    // reduce (sp, sum, sq) across block
    #pragma unroll
    for (int off = 16; off > 0; off >>= 1) {
        sp  += __shfl_down_sync(0xFFFFFFFFu, sp,  off);
        sum += __shfl_down_sync(0xFFFFFFFFu, sum, off);
        sq  += __shfl_down_sync(0xFFFFFFFFu, sq,  off);
    }
    __shared__ float red[3][8];
    __shared__ float bc[3];
    const int lane = threadIdx.x & 31;
    const int w    = threadIdx.x >> 5;
    if (lane == 0) { red[0][w] = sp; red[1][w] = sum; red[2][w] = sq; }
    __syncthreads();
    if (threadIdx.x == 0) {
        float S = 0, SU = 0, SQ = 0;
        #pragma unroll
        for (int i = 0; i < 8; i++) { S += red[0][i]; SU += red[1][i]; SQ += red[2][i]; }
        bc[0] = S; bc[1] = SU; bc[2] = SQ;
    }
    __syncthreads();

    const float s     = bc[0];
    const float total = bc[1] + s;
    const float totsq = bc[2] + s * s;
    const float inv   = 1.0f / 4097.0f;
    const float mean  = total * inv;
    const float var   = totsq * inv - mean * mean;
    const float rstd  = rsqrtf(var + 1e-5f);

    float* xr = xn + (size_t)n * HIDDEN;
    #pragma unroll
    for (int i = 0; i < 4; i++) {
        const int c = threadIdx.x + i * 256;
        xr[c]          = (va[i] - mean) * rstd * ln_g[c]          + ln_b[c];
        xr[1024 + c]   = (vb[i] - mean) * rstd * ln_g[1024 + c]   + ln_b[1024 + c];
        xr[2048 + c]   = (vh[i] - mean) * rstd * ln_g[2048 + c]   + ln_b[2048 + c];
        xr[3072 + c]   = (vd[i] - mean) * rstd * ln_g[3072 + c]   + ln_b[3072 + c];
    }
    if (threadIdx.x == 0)
        sn[n] = (s - mean) * rstd * ln_g[4096] + ln_b[4096];
}

// ---------------------------------------------------------------------------
extern "C" void kernel_launch(void* const* d_in, const int* in_sizes, int n_in,
                              void* d_out, int out_size)
{
    const float* zA   = (const float*)d_in[0];
    const float* zB   = (const float*)d_in[1];
    const float* bil  = (const float*)d_in[2];
    const float* ln_g = (const float*)d_in[3];
    const float* ln_b = (const float*)d_in[4];
    const float* W1   = (const float*)d_in[5];
    const float* b1   = (const float*)d_in[6];
    const float* W2   = (const float*)d_in[7];
    const float* b2   = (const float*)d_in[8];
    float* out = (float*)d_out;

    float *t, *xn, *sn, *h;
    cudaGetSymbolAddress((void**)&t,  g_t);
    cudaGetSymbolAddress((void**)&xn, g_xn);
    cudaGetSymbolAddress((void**)&sn, g_sn);
    cudaGetSymbolAddress((void**)&h,  g_h);

    // 1) t = zA @ bilinear   [16384,1024] = [16384,1024]@[1024,1024]
    {
        dim3 grid(DIM / 128, N_ROWS / 128);
        sgemm_kernel<0><<<grid, 256>>>(zA, bil, t, N_ROWS, DIM, DIM,
                                       nullptr, nullptr, nullptr);
    }

    // 2) s + LayerNorm, producing x_norm[:,4096] and s_norm
    row_fuse_kernel<<<N_ROWS, 256>>>(zA, zB, t, ln_g, ln_b, xn, sn);

    // 3) h = gelu(x_norm @ W1[:4096] + s_norm * W1[4096,:] + b1)
    {
        dim3 grid(HIDDEN / 128, N_ROWS / 128);
        const float* w_last = W1 + (size_t)4096 * HIDDEN;  // row 4096 of W1
        sgemm_kernel<1><<<grid, 256>>>(xn, W1, h, N_ROWS, HIDDEN, HIDDEN,
                                       b1, w_last, sn);
    }

    // 4) out = gelu(h @ W2 + b2)   [16384,1024]
    {
        dim3 grid(DIM / 128, N_ROWS / 128);
        sgemm_kernel<2><<<grid, 256>>>(h, W2, out, N_ROWS, DIM, HIDDEN,
                                       b2, nullptr, nullptr);
    }
}

// round 3
// speedup vs baseline: 1.7437x; 1.7437x over previous
#include <cuda_runtime.h>
#include <cuda_bf16.h>
#include <math.h>
#include <stdint.h>

#define N_ROWS 16384
#define DIM    1024
#define HIDDEN 4096

typedef __nv_bfloat16 bf16;

// ---------------------------------------------------------------------------
// Scratch (static device globals — allocation-free per harness rules)
// ---------------------------------------------------------------------------
__device__ __align__(128) bf16  g_zA_h [(size_t)N_ROWS * DIM];
__device__ __align__(128) bf16  g_zA_l [(size_t)N_ROWS * DIM];
__device__ __align__(128) bf16  g_bilT_h[(size_t)DIM * DIM];
__device__ __align__(128) bf16  g_bilT_l[(size_t)DIM * DIM];
__device__ __align__(128) bf16  g_w1t_h[(size_t)HIDDEN * HIDDEN];
__device__ __align__(128) bf16  g_w1t_l[(size_t)HIDDEN * HIDDEN];
__device__ __align__(128) bf16  g_w2t_h[(size_t)DIM * HIDDEN];
__device__ __align__(128) bf16  g_w2t_l[(size_t)DIM * HIDDEN];
__device__ __align__(128) float g_t    [(size_t)N_ROWS * DIM];
__device__ __align__(128) bf16  g_xn_h [(size_t)N_ROWS * HIDDEN];
__device__ __align__(128) bf16  g_xn_l [(size_t)N_ROWS * HIDDEN];
__device__ __align__(128) bf16  g_h_h  [(size_t)N_ROWS * HIDDEN];
__device__ __align__(128) bf16  g_h_l  [(size_t)N_ROWS * HIDDEN];
__device__ __align__(128) float g_sn   [N_ROWS];

// ---------------------------------------------------------------------------
// Baseline-PTX helpers (sm_80-era features only: cp.async, ldmatrix, mma.sync)
// ---------------------------------------------------------------------------
__device__ __forceinline__ uint32_t smem_u32(const void* p) {
    uint32_t a;
    asm("{ .reg .u64 t; cvta.to.shared.u64 t, %1; cvt.u32.u64 %0, t; }"
        : "=r"(a) : "l"(p));
    return a;
}

#define CP16(dst, src) \
    asm volatile("cp.async.cg.shared.global [%0], [%1], 16;" \
        :: "r"(dst), "l"(src))
#define CP_COMMIT() asm volatile("cp.async.commit_group;" ::: "memory")
#define CP_WAIT1()  asm volatile("cp.async.wait_group 1;" ::: "memory")
#define CP_WAIT0()  asm volatile("cp.async.wait_group 0;" ::: "memory")

#define LDSM_X4(r, addr) \
    asm volatile("ldmatrix.sync.aligned.m8n8.x4.shared.b16 {%0,%1,%2,%3}, [%4];" \
        : "=r"((r)[0]), "=r"((r)[1]), "=r"((r)[2]), "=r"((r)[3]) : "r"(addr))

__device__ __forceinline__ void mma_bf16(float* d, const uint32_t* a,
                                         uint32_t b0, uint32_t b1) {
    asm volatile(
        "mma.sync.aligned.m16n8k16.row.col.f32.bf16.bf16.f32 "
        "{%0,%1,%2,%3}, {%4,%5,%6,%7}, {%8,%9}, {%0,%1,%2,%3};"
        : "+f"(d[0]), "+f"(d[1]), "+f"(d[2]), "+f"(d[3])
        : "r"(a[0]), "r"(a[1]), "r"(a[2]), "r"(a[3]), "r"(b0), "r"(b1));
}

__device__ __forceinline__ float gelu_exact(float x) {
    return 0.5f * x * (1.0f + erff(x * 0.70710678118654752440f));
}

// ---------------------------------------------------------------------------
// mma.sync GEMM, 3xBF16 split precision.
// D[M,Ncols] = (Ah+Al)[M,K] @ (Bh+Bl)[Ncols,K]^T   (B stored transposed [N,K])
// BM=BN=128, BK=32, 8 warps (2x4), warp tile 64x32, 3-stage cp.async pipeline.
// SMEM row pitch 80B (64B data + 16B pad) -> conflict-free ldmatrix.
// MODE 0: Cf = acc (fp32)
// MODE 1: g = gelu(acc + svec[r]*wlast[c] + bias[c]) -> Ch/Cl bf16 hi/lo split
// MODE 2: Cf = gelu(acc + bias[c])
// ---------------------------------------------------------------------------
#define PLANE_B 10240            // 128 rows * 80B
#define STAGE_B (4 * PLANE_B)    // Ah, Al, Bh, Bl
#define NSTAGE  3
#define GSM_BYTES (NSTAGE * STAGE_B)

__device__ __forceinline__ void load_stage(
    uint32_t sb, int stage,
    const bf16* __restrict__ Ah, const bf16* __restrict__ Al,
    const bf16* __restrict__ Bh, const bf16* __restrict__ Bl,
    int row0, int col0, int k0, int K, int tid)
{
    const uint32_t s0 = sb + stage * STAGE_B;
    #pragma unroll
    for (int j = 0; j < 8; j++) {
        const int ci    = tid + j * 256;
        const int plane = ci >> 9;          // = j>>1 (const per j)
        const int row   = (ci >> 2) & 127;
        const int ch    = ci & 3;
        const size_t go = (size_t)((plane < 2 ? row0 : col0) + row) * K + k0 + ch * 8;
        const bf16* src = (plane == 0) ? Ah + go :
                          (plane == 1) ? Al + go :
                          (plane == 2) ? Bh + go : Bl + go;
        const uint32_t so = s0 + plane * PLANE_B + row * 80 + ((ch ^ (row & 3)) << 4);
        CP16(so, src);
    }
    CP_COMMIT();
}

template <int MODE>
__global__ __launch_bounds__(256, 1)
void gemm_mma(const bf16* __restrict__ Ah, const bf16* __restrict__ Al,
              const bf16* __restrict__ Bh, const bf16* __restrict__ Bl,
              int K, int Ncols,
              float* __restrict__ Cf, bf16* __restrict__ Ch, bf16* __restrict__ Cl,
              const float* __restrict__ bias, const float* __restrict__ wlast,
              const float* __restrict__ svec)
{
    extern __shared__ __align__(128) char smem[];
    const uint32_t sb = smem_u32(smem);
    const int tid  = threadIdx.x;
    const int lane = tid & 31;
    const int warp = tid >> 5;
    const int wm   = warp & 1;     // 0..1 -> 64-row panel
    const int wn   = warp >> 1;    // 0..3 -> 32-col panel
    const int row0 = blockIdx.y * 128;
    const int col0 = blockIdx.x * 128;

    const int nch = K >> 5;

    load_stage(sb, 0, Ah, Al, Bh, Bl, row0, col0, 0,  K, tid);
    load_stage(sb, 1, Ah, Al, Bh, Bl, row0, col0, 32, K, tid);

    float acc[4][4][4];
    #pragma unroll
    for (int a = 0; a < 4; a++)
        #pragma unroll
        for (int b = 0; b < 4; b++)
            #pragma unroll
            for (int c = 0; c < 4; c++) acc[a][b][c] = 0.0f;

    // ldmatrix lane geometry
    const int arow = wm * 64 + (lane & 7) + ((lane >> 3) & 1) * 8;  // M row
    const int ak   = lane >> 4;                                      // k chunk half
    const int brow = wn * 32 + (lane & 7) + ((lane >> 4) & 1) * 8;  // N row
    const int bk   = (lane >> 3) & 1;

    for (int i = 0; i < nch; i++) {
        if (i + 1 < nch) { CP_WAIT1(); } else { CP_WAIT0(); }
        __syncthreads();
        if (i + 2 < nch)
            load_stage(sb, (i + 2) % NSTAGE, Ah, Al, Bh, Bl,
                       row0, col0, (i + 2) << 5, K, tid);

        const uint32_t st = sb + (i % NSTAGE) * STAGE_B;
        #pragma unroll
        for (int ks = 0; ks < 2; ks++) {
            uint32_t ahf[4][4], alf[4][4];
            #pragma unroll
            for (int mi = 0; mi < 4; mi++) {
                const uint32_t ra = st + (arow + mi * 16) * 80 +
                                    (((ks * 2 + ak) ^ (arow & 3)) << 4);
                LDSM_X4(ahf[mi], ra);
                LDSM_X4(alf[mi], ra + PLANE_B);
            }
            #pragma unroll
            for (int np = 0; np < 2; np++) {
                const uint32_t rb = st + 2 * PLANE_B + (brow + np * 16) * 80 +
                                    (((ks * 2 + bk) ^ (brow & 3)) << 4);
                uint32_t bhf[4], blf[4];
                LDSM_X4(bhf, rb);
                LDSM_X4(blf, rb + PLANE_B);
                #pragma unroll
                for (int mi = 0; mi < 4; mi++) {
                    mma_bf16(acc[mi][np * 2 + 0], ahf[mi], bhf[0], bhf[1]);
                    mma_bf16(acc[mi][np * 2 + 0], ahf[mi], blf[0], blf[1]);
                    mma_bf16(acc[mi][np * 2 + 0], alf[mi], bhf[0], bhf[1]);
                    mma_bf16(acc[mi][np * 2 + 1], ahf[mi], bhf[2], bhf[3]);
                    mma_bf16(acc[mi][np * 2 + 1], ahf[mi], blf[2], blf[3]);
                    mma_bf16(acc[mi][np * 2 + 1], alf[mi], bhf[2], bhf[3]);
                }
            }
        }
    }

    // Epilogue. acc layout per mma: c0,c1 -> (r, c..c+1); c2,c3 -> (r+8, c..c+1)
    const int r_base = row0 + wm * 64 + (lane >> 2);
    const int c_base = col0 + wn * 32 + (lane & 3) * 2;

    #pragma unroll
    for (int mi = 0; mi < 4; mi++) {
        const int r = r_base + mi * 16;
        float sv0 = 0.0f, sv1 = 0.0f;
        if (MODE == 1) { sv0 = __ldg(svec + r); sv1 = __ldg(svec + r + 8); }
        #pragma unroll
        for (int ni = 0; ni < 4; ni++) {
            const int c = c_base + ni * 8;
            float v0 = acc[mi][ni][0], v1 = acc[mi][ni][1];
            float v2 = acc[mi][ni][2], v3 = acc[mi][ni][3];
            if (MODE == 0) {
                *reinterpret_cast<float2*>(Cf + (size_t)r * Ncols + c)       = make_float2(v0, v1);
                *reinterpret_cast<float2*>(Cf + (size_t)(r + 8) * Ncols + c) = make_float2(v2, v3);
            } else if (MODE == 2) {
                const float bb0 = __ldg(bias + c), bb1 = __ldg(bias + c + 1);
                *reinterpret_cast<float2*>(Cf + (size_t)r * Ncols + c) =
                    make_float2(gelu_exact(v0 + bb0), gelu_exact(v1 + bb1));
                *reinterpret_cast<float2*>(Cf + (size_t)(r + 8) * Ncols + c) =
                    make_float2(gelu_exact(v2 + bb0), gelu_exact(v3 + bb1));
            } else {
                const float bb0 = __ldg(bias + c), bb1 = __ldg(bias + c + 1);
                const float wl0 = __ldg(wlast + c), wl1 = __ldg(wlast + c + 1);
                float g0 = gelu_exact(v0 + sv0 * wl0 + bb0);
                float g1 = gelu_exact(v1 + sv0 * wl1 + bb1);
                float g2 = gelu_exact(v2 + sv1 * wl0 + bb0);
                float g3 = gelu_exact(v3 + sv1 * wl1 + bb1);
                union { bf16 e[2]; uint32_t u; } H0, H1, L0, L1;
                H0.e[0] = __float2bfloat16(g0);
                H0.e[1] = __float2bfloat16(g1);
                L0.e[0] = __float2bfloat16(g0 - __bfloat162float(H0.e[0]));
                L0.e[1] = __float2bfloat16(g1 - __bfloat162float(H0.e[1]));
                H1.e[0] = __float2bfloat16(g2);
                H1.e[1] = __float2bfloat16(g3);
                L1.e[0] = __float2bfloat16(g2 - __bfloat162float(H1.e[0]));
                L1.e[1] = __float2bfloat16(g3 - __bfloat162float(H1.e[1]));
                *reinterpret_cast<uint32_t*>(Ch + (size_t)r * Ncols + c)       = H0.u;
                *reinterpret_cast<uint32_t*>(Cl + (size_t)r * Ncols + c)       = L0.u;
                *reinterpret_cast<uint32_t*>(Ch + (size_t)(r + 8) * Ncols + c) = H1.u;
                *reinterpret_cast<uint32_t*>(Cl + (size_t)(r + 8) * Ncols + c) = L1.u;
            }
        }
    }
}

// ---------------------------------------------------------------------------
// fp32 -> bf16 hi/lo split (elementwise, vectorized)
// ---------------------------------------------------------------------------
__global__ __launch_bounds__(256)
void split_kernel(const float* __restrict__ in, bf16* __restrict__ oh,
                  bf16* __restrict__ ol, int n4)
{
    const int i = blockIdx.x * 256 + threadIdx.x;
    if (i >= n4) return;
    float4 v = reinterpret_cast<const float4*>(in)[i];
    union { bf16 e[4]; uint2 u; } H, L;
    H.e[0] = __float2bfloat16(v.x); L.e[0] = __float2bfloat16(v.x - __bfloat162float(H.e[0]));
    H.e[1] = __float2bfloat16(v.y); L.e[1] = __float2bfloat16(v.y - __bfloat162float(H.e[1]));
    H.e[2] = __float2bfloat16(v.z); L.e[2] = __float2bfloat16(v.z - __bfloat162float(H.e[2]));
    H.e[3] = __float2bfloat16(v.w); L.e[3] = __float2bfloat16(v.w - __bfloat162float(H.e[3]));
    reinterpret_cast<uint2*>(oh)[i] = H.u;
    reinterpret_cast<uint2*>(ol)[i] = L.u;
}

// in [R,C] fp32 row-major -> out [C,R] bf16 hi/lo (transpose + split)
__global__ __launch_bounds__(256)
void transpose_split_kernel(const float* __restrict__ in, bf16* __restrict__ oh,
                            bf16* __restrict__ ol, int R, int C)
{
    __shared__ float tile[32][33];
    const int c  = blockIdx.x * 32 + threadIdx.x;
    const int r0 = blockIdx.y * 32;
    #pragma unroll
    for (int i = threadIdx.y; i < 32; i += 8)
        tile[i][threadIdx.x] = in[(size_t)(r0 + i) * C + c];
    __syncthreads();
    const int rr = r0 + threadIdx.x;       // output column (= input row)
    const int cc = blockIdx.x * 32;        // output row base (= input col)
    #pragma unroll
    for (int i = threadIdx.y; i < 32; i += 8) {
        float v = tile[threadIdx.x][i];
        bf16 h = __float2bfloat16(v);
        oh[(size_t)(cc + i) * R + rr] = h;
        ol[(size_t)(cc + i) * R + rr] = __float2bfloat16(v - __bfloat162float(h));
    }
}

// ---------------------------------------------------------------------------
// Per-row fusion: s = dot(t_row, zB_row); LN over 4097 virtual features;
// emit normalized x (4096 cols) as bf16 hi/lo planes + normalized s (fp32).
// ---------------------------------------------------------------------------
__global__ __launch_bounds__(256)
void row_fuse_kernel(const float* __restrict__ zA, const float* __restrict__ zB,
                     const float* __restrict__ t,
                     const float* __restrict__ ln_g, const float* __restrict__ ln_b,
                     bf16* __restrict__ xh, bf16* __restrict__ xl,
                     float* __restrict__ sn)
{
    const int n = blockIdx.x;
    const float* a  = zA + (size_t)n * DIM;
    const float* b  = zB + (size_t)n * DIM;
    const float* tt = t  + (size_t)n * DIM;

    float va[4], vb[4], vh[4], vd[4];
    float sp = 0.0f, sum = 0.0f, sq = 0.0f;

    #pragma unroll
    for (int i = 0; i < 4; i++) {
        const int c = threadIdx.x + i * 256;
        float x1 = a[c], x2 = b[c];
        float hd = x1 * x2;
        float df = fabsf(x1 - x2);
        va[i] = x1; vb[i] = x2; vh[i] = hd; vd[i] = df;
        sp  = fmaf(tt[c], x2, sp);
        sum += x1 + x2 + hd + df;
        sq  = fmaf(x1, x1, sq); sq = fmaf(x2, x2, sq);
        sq  = fmaf(hd, hd, sq); sq = fmaf(df, df, sq);
    }

    #pragma unroll
    for (int off = 16; off > 0; off >>= 1) {
        sp  += __shfl_down_sync(0xFFFFFFFFu, sp,  off);
        sum += __shfl_down_sync(0xFFFFFFFFu, sum, off);
        sq  += __shfl_down_sync(0xFFFFFFFFu, sq,  off);
    }
    __shared__ float red[3][8];
    __shared__ float bc[3];
    const int lane = threadIdx.x & 31;
    const int w    = threadIdx.x >> 5;
    if (lane == 0) { red[0][w] = sp; red[1][w] = sum; red[2][w] = sq; }
    __syncthreads();
    if (threadIdx.x == 0) {
        float S = 0, SU = 0, SQ = 0;
        #pragma unroll
        for (int i = 0; i < 8; i++) { S += red[0][i]; SU += red[1][i]; SQ += red[2][i]; }
        bc[0] = S; bc[1] = SU; bc[2] = SQ;
    }
    __syncthreads();

    const float s     = bc[0];
    const float total = bc[1] + s;
    const float totsq = bc[2] + s * s;
    const float inv   = 1.0f / 4097.0f;
    const float mean  = total * inv;
    const float var   = totsq * inv - mean * mean;
    const float rstd  = rsqrtf(var + 1e-5f);

    bf16* xhr = xh + (size_t)n * HIDDEN;
    bf16* xlr = xl + (size_t)n * HIDDEN;
    #pragma unroll
    for (int i = 0; i < 4; i++) {
        const int c = threadIdx.x + i * 256;
        #pragma unroll
        for (int seg = 0; seg < 4; seg++) {
            const int cc = seg * 1024 + c;
            float vsrc = (seg == 0) ? va[i] : (seg == 1) ? vb[i] : (seg == 2) ? vh[i] : vd[i];
            float v = (vsrc - mean) * rstd * ln_g[cc] + ln_b[cc];
            bf16 hb = __float2bfloat16(v);
            xhr[cc] = hb;
            xlr[cc] = __float2bfloat16(v - __bfloat162float(hb));
        }
    }
    if (threadIdx.x == 0)
        sn[n] = (s - mean) * rstd * ln_g[4096] + ln_b[4096];
}

// ---------------------------------------------------------------------------
extern "C" void kernel_launch(void* const* d_in, const int* in_sizes, int n_in,
                              void* d_out, int out_size)
{
    const float* zA   = (const float*)d_in[0];
    const float* zB   = (const float*)d_in[1];
    const float* bil  = (const float*)d_in[2];
    const float* ln_g = (const float*)d_in[3];
    const float* ln_b = (const float*)d_in[4];
    const float* W1   = (const float*)d_in[5];
    const float* b1   = (const float*)d_in[6];
    const float* W2   = (const float*)d_in[7];
    const float* b2   = (const float*)d_in[8];
    float* out = (float*)d_out;

    bf16 *zA_h, *zA_l, *bilT_h, *bilT_l, *w1t_h, *w1t_l, *w2t_h, *w2t_l;
    bf16 *xn_h, *xn_l, *h_h, *h_l;
    float *t, *sn;
    cudaGetSymbolAddress((void**)&zA_h,  g_zA_h);
    cudaGetSymbolAddress((void**)&zA_l,  g_zA_l);
    cudaGetSymbolAddress((void**)&bilT_h, g_bilT_h);
    cudaGetSymbolAddress((void**)&bilT_l, g_bilT_l);
    cudaGetSymbolAddress((void**)&w1t_h, g_w1t_h);
    cudaGetSymbolAddress((void**)&w1t_l, g_w1t_l);
    cudaGetSymbolAddress((void**)&w2t_h, g_w2t_h);
    cudaGetSymbolAddress((void**)&w2t_l, g_w2t_l);
    cudaGetSymbolAddress((void**)&t,     g_t);
    cudaGetSymbolAddress((void**)&xn_h,  g_xn_h);
    cudaGetSymbolAddress((void**)&xn_l,  g_xn_l);
    cudaGetSymbolAddress((void**)&h_h,   g_h_h);
    cudaGetSymbolAddress((void**)&h_l,   g_h_l);
    cudaGetSymbolAddress((void**)&sn,    g_sn);

    cudaFuncSetAttribute(gemm_mma<0>, cudaFuncAttributeMaxDynamicSharedMemorySize, GSM_BYTES);
    cudaFuncSetAttribute(gemm_mma<1>, cudaFuncAttributeMaxDynamicSharedMemorySize, GSM_BYTES);
    cudaFuncSetAttribute(gemm_mma<2>, cudaFuncAttributeMaxDynamicSharedMemorySize, GSM_BYTES);

    // 0) operand conversions
    split_kernel<<<(N_ROWS * DIM / 4 + 255) / 256, 256>>>(zA, zA_h, zA_l, N_ROWS * DIM / 4);
    transpose_split_kernel<<<dim3(DIM / 32, DIM / 32), dim3(32, 8)>>>(bil, bilT_h, bilT_l, DIM, DIM);
    transpose_split_kernel<<<dim3(HIDDEN / 32, HIDDEN / 32), dim3(32, 8)>>>(W1, w1t_h, w1t_l, HIDDEN, HIDDEN);
    transpose_split_kernel<<<dim3(DIM / 32, HIDDEN / 32), dim3(32, 8)>>>(W2, w2t_h, w2t_l, HIDDEN, DIM);

    // 1) t = zA @ bilinear   [16384,1024]
    gemm_mma<0><<<dim3(DIM / 128, N_ROWS / 128), 256, GSM_BYTES>>>(
        zA_h, zA_l, bilT_h, bilT_l, DIM, DIM, t, nullptr, nullptr,
        nullptr, nullptr, nullptr);

    // 2) s + LayerNorm -> xn (bf16 hi/lo), sn
    row_fuse_kernel<<<N_ROWS, 256>>>(zA, zB, t, ln_g, ln_b, xn_h, xn_l, sn);

    // 3) h = gelu(xn @ W1[:4096] + sn*W1[4096,:] + b1)  (bf16 hi/lo out)
    gemm_mma<1><<<dim3(HIDDEN / 128, N_ROWS / 128), 256, GSM_BYTES>>>(
        xn_h, xn_l, w1t_h, w1t_l, HIDDEN, HIDDEN, nullptr, h_h, h_l,
        b1, W1 + (size_t)4096 * HIDDEN, sn);

    // 4) out = gelu(h @ W2 + b2)  (fp32)
    gemm_mma<2><<<dim3(DIM / 128, N_ROWS / 128), 256, GSM_BYTES>>>(
        h_h, h_l, w2t_h, w2t_l, HIDDEN, DIM, out, nullptr, nullptr,
        b2, nullptr, nullptr);
}

// round 4
// speedup vs baseline: 2.0815x; 1.1937x over previous
#include <cuda_runtime.h>
#include <cuda_bf16.h>
#include <math.h>
#include <stdint.h>

#define N_ROWS 16384
#define DIM    1024
#define HIDDEN 4096

typedef __nv_bfloat16 bf16;

// ---------------------------------------------------------------------------
// Scratch (static device globals — allocation-free per harness rules)
// ---------------------------------------------------------------------------
__device__ __align__(128) bf16  g_zA_h [(size_t)N_ROWS * DIM];
__device__ __align__(128) bf16  g_zA_l [(size_t)N_ROWS * DIM];
__device__ __align__(128) bf16  g_bilT_h[(size_t)DIM * DIM];
__device__ __align__(128) bf16  g_bilT_l[(size_t)DIM * DIM];
__device__ __align__(128) bf16  g_w1t_h[(size_t)HIDDEN * HIDDEN];
__device__ __align__(128) bf16  g_w1t_l[(size_t)HIDDEN * HIDDEN];
__device__ __align__(128) bf16  g_w2t_h[(size_t)DIM * HIDDEN];
__device__ __align__(128) bf16  g_w2t_l[(size_t)DIM * HIDDEN];
__device__ __align__(128) float g_t    [(size_t)N_ROWS * DIM];
__device__ __align__(128) bf16  g_xn_h [(size_t)N_ROWS * HIDDEN];
__device__ __align__(128) bf16  g_xn_l [(size_t)N_ROWS * HIDDEN];
__device__ __align__(128) bf16  g_h_h  [(size_t)N_ROWS * HIDDEN];
__device__ __align__(128) bf16  g_h_l  [(size_t)N_ROWS * HIDDEN];
__device__ __align__(128) float g_sn   [N_ROWS];

// ---------------------------------------------------------------------------
// Baseline-PTX helpers (sm_80-era features only: cp.async, ldmatrix, mma.sync)
// ---------------------------------------------------------------------------
__device__ __forceinline__ uint32_t smem_u32(const void* p) {
    uint32_t a;
    asm("{ .reg .u64 t; cvta.to.shared.u64 t, %1; cvt.u32.u64 %0, t; }"
        : "=r"(a) : "l"(p));
    return a;
}

#define CP16(dst, src) \
    asm volatile("cp.async.cg.shared.global [%0], [%1], 16;" \
        :: "r"(dst), "l"(src))
#define CP_COMMIT() asm volatile("cp.async.commit_group;" ::: "memory")
#define CP_WAIT0()  asm volatile("cp.async.wait_group 0;" ::: "memory")

#define LDSM_X4(r, addr) \
    asm volatile("ldmatrix.sync.aligned.m8n8.x4.shared.b16 {%0,%1,%2,%3}, [%4];" \
        : "=r"((r)[0]), "=r"((r)[1]), "=r"((r)[2]), "=r"((r)[3]) : "r"(addr))

__device__ __forceinline__ void mma_bf16(float* d, const uint32_t* a,
                                         uint32_t b0, uint32_t b1) {
    asm volatile(
        "mma.sync.aligned.m16n8k16.row.col.f32.bf16.bf16.f32 "
        "{%0,%1,%2,%3}, {%4,%5,%6,%7}, {%8,%9}, {%0,%1,%2,%3};"
        : "+f"(d[0]), "+f"(d[1]), "+f"(d[2]), "+f"(d[3])
        : "r"(a[0]), "r"(a[1]), "r"(a[2]), "r"(a[3]), "r"(b0), "r"(b1));
}

__device__ __forceinline__ float gelu_exact(float x) {
    return 0.5f * x * (1.0f + erff(x * 0.70710678118654752440f));
}

// ---------------------------------------------------------------------------
// mma.sync GEMM, 3xBF16 split precision.
// D[M,Ncols] = (Ah+Al)[M,K] @ (Bh+Bl)[Ncols,K]^T   (B stored transposed [N,K])
// BM=BN=128, BK=32, 8 warps (2x4), warp tile 64x32.
// 2-stage cp.async pipeline, 2 CTAs/SM (80KB smem each) -> 16 warps/SM.
// SMEM row pitch 80B (64B data + 16B pad) -> conflict-free ldmatrix.
// MODE 0: Cf = acc (fp32)
// MODE 1: g = gelu(acc + svec[r]*wlast[c] + bias[c]) -> Ch/Cl bf16 hi/lo split
// MODE 2: Cf = gelu(acc + bias[c])
// ---------------------------------------------------------------------------
#define PLANE_B 10240            // 128 rows * 80B
#define STAGE_B (4 * PLANE_B)    // Ah, Al, Bh, Bl
#define NSTAGE  2
#define GSM_BYTES (NSTAGE * STAGE_B)

__device__ __forceinline__ void load_stage(
    uint32_t sb, int stage,
    const bf16* __restrict__ Ah, const bf16* __restrict__ Al,
    const bf16* __restrict__ Bh, const bf16* __restrict__ Bl,
    int row0, int col0, int k0, int K, int tid)
{
    const uint32_t s0 = sb + stage * STAGE_B;
    #pragma unroll
    for (int j = 0; j < 8; j++) {
        const int ci    = tid + j * 256;
        const int plane = ci >> 9;          // = j>>1 (const per j)
        const int row   = (ci >> 2) & 127;
        const int ch    = ci & 3;
        const size_t go = (size_t)((plane < 2 ? row0 : col0) + row) * K + k0 + ch * 8;
        const bf16* src = (plane == 0) ? Ah + go :
                          (plane == 1) ? Al + go :
                          (plane == 2) ? Bh + go : Bl + go;
        const uint32_t so = s0 + plane * PLANE_B + row * 80 + ((ch ^ (row & 3)) << 4);
        CP16(so, src);
    }
    CP_COMMIT();
}

template <int MODE>
__global__ __launch_bounds__(256, 2)
void gemm_mma(const bf16* __restrict__ Ah, const bf16* __restrict__ Al,
              const bf16* __restrict__ Bh, const bf16* __restrict__ Bl,
              int K, int Ncols,
              float* __restrict__ Cf, bf16* __restrict__ Ch, bf16* __restrict__ Cl,
              const float* __restrict__ bias, const float* __restrict__ wlast,
              const float* __restrict__ svec)
{
    extern __shared__ __align__(128) char smem[];
    const uint32_t sb = smem_u32(smem);
    const int tid  = threadIdx.x;
    const int lane = tid & 31;
    const int warp = tid >> 5;
    const int wm   = warp & 1;     // 0..1 -> 64-row panel
    const int wn   = warp >> 1;    // 0..3 -> 32-col panel
    const int row0 = blockIdx.y * 128;
    const int col0 = blockIdx.x * 128;

    const int nch = K >> 5;

    load_stage(sb, 0, Ah, Al, Bh, Bl, row0, col0, 0, K, tid);

    float acc[4][4][4];
    #pragma unroll
    for (int a = 0; a < 4; a++)
        #pragma unroll
        for (int b = 0; b < 4; b++)
            #pragma unroll
            for (int c = 0; c < 4; c++) acc[a][b][c] = 0.0f;

    // ldmatrix lane geometry
    const int arow = wm * 64 + (lane & 7) + ((lane >> 3) & 1) * 8;  // M row
    const int ak   = lane >> 4;                                      // k chunk half
    const int brow = wn * 32 + (lane & 7) + ((lane >> 4) & 1) * 8;  // N row
    const int bk   = (lane >> 3) & 1;

    for (int i = 0; i < nch; i++) {
        CP_WAIT0();            // chunk i resident
        __syncthreads();       // visible to all warps; prior stage fully consumed
        if (i + 1 < nch)       // overlap next load with compute of chunk i
            load_stage(sb, (i + 1) & 1, Ah, Al, Bh, Bl,
                       row0, col0, (i + 1) << 5, K, tid);

        const uint32_t st = sb + (i & 1) * STAGE_B;
        #pragma unroll
        for (int ks = 0; ks < 2; ks++) {
            uint32_t ahf[4][4], alf[4][4];
            #pragma unroll
            for (int mi = 0; mi < 4; mi++) {
                const uint32_t ra = st + (arow + mi * 16) * 80 +
                                    (((ks * 2 + ak) ^ (arow & 3)) << 4);
                LDSM_X4(ahf[mi], ra);
                LDSM_X4(alf[mi], ra + PLANE_B);
            }
            #pragma unroll
            for (int np = 0; np < 2; np++) {
                const uint32_t rb = st + 2 * PLANE_B + (brow + np * 16) * 80 +
                                    (((ks * 2 + bk) ^ (brow & 3)) << 4);
                uint32_t bhf[4], blf[4];
                LDSM_X4(bhf, rb);
                LDSM_X4(blf, rb + PLANE_B);
                #pragma unroll
                for (int mi = 0; mi < 4; mi++) {
                    mma_bf16(acc[mi][np * 2 + 0], ahf[mi], bhf[0], bhf[1]);
                    mma_bf16(acc[mi][np * 2 + 0], ahf[mi], blf[0], blf[1]);
                    mma_bf16(acc[mi][np * 2 + 0], alf[mi], bhf[0], bhf[1]);
                    mma_bf16(acc[mi][np * 2 + 1], ahf[mi], bhf[2], bhf[3]);
                    mma_bf16(acc[mi][np * 2 + 1], ahf[mi], blf[2], blf[3]);
                    mma_bf16(acc[mi][np * 2 + 1], alf[mi], bhf[2], bhf[3]);
                }
            }
        }
        __syncthreads();       // all warps done with stage (i&1) before it is refilled
    }

    // Epilogue. acc layout per mma: c0,c1 -> (r, c..c+1); c2,c3 -> (r+8, c..c+1)
    const int r_base = row0 + wm * 64 + (lane >> 2);
    const int c_base = col0 + wn * 32 + (lane & 3) * 2;

    #pragma unroll
    for (int mi = 0; mi < 4; mi++) {
        const int r = r_base + mi * 16;
        float sv0 = 0.0f, sv1 = 0.0f;
        if (MODE == 1) { sv0 = __ldg(svec + r); sv1 = __ldg(svec + r + 8); }
        #pragma unroll
        for (int ni = 0; ni < 4; ni++) {
            const int c = c_base + ni * 8;
            float v0 = acc[mi][ni][0], v1 = acc[mi][ni][1];
            float v2 = acc[mi][ni][2], v3 = acc[mi][ni][3];
            if (MODE == 0) {
                *reinterpret_cast<float2*>(Cf + (size_t)r * Ncols + c)       = make_float2(v0, v1);
                *reinterpret_cast<float2*>(Cf + (size_t)(r + 8) * Ncols + c) = make_float2(v2, v3);
            } else if (MODE == 2) {
                const float bb0 = __ldg(bias + c), bb1 = __ldg(bias + c + 1);
                *reinterpret_cast<float2*>(Cf + (size_t)r * Ncols + c) =
                    make_float2(gelu_exact(v0 + bb0), gelu_exact(v1 + bb1));
                *reinterpret_cast<float2*>(Cf + (size_t)(r + 8) * Ncols + c) =
                    make_float2(gelu_exact(v2 + bb0), gelu_exact(v3 + bb1));
            } else {
                const float bb0 = __ldg(bias + c), bb1 = __ldg(bias + c + 1);
                const float wl0 = __ldg(wlast + c), wl1 = __ldg(wlast + c + 1);
                float g0 = gelu_exact(v0 + sv0 * wl0 + bb0);
                float g1 = gelu_exact(v1 + sv0 * wl1 + bb1);
                float g2 = gelu_exact(v2 + sv1 * wl0 + bb0);
                float g3 = gelu_exact(v3 + sv1 * wl1 + bb1);
                union { bf16 e[2]; uint32_t u; } H0, H1, L0, L1;
                H0.e[0] = __float2bfloat16(g0);
                H0.e[1] = __float2bfloat16(g1);
                L0.e[0] = __float2bfloat16(g0 - __bfloat162float(H0.e[0]));
                L0.e[1] = __float2bfloat16(g1 - __bfloat162float(H0.e[1]));
                H1.e[0] = __float2bfloat16(g2);
                H1.e[1] = __float2bfloat16(g3);
                L1.e[0] = __float2bfloat16(g2 - __bfloat162float(H1.e[0]));
                L1.e[1] = __float2bfloat16(g3 - __bfloat162float(H1.e[1]));
                *reinterpret_cast<uint32_t*>(Ch + (size_t)r * Ncols + c)       = H0.u;
                *reinterpret_cast<uint32_t*>(Cl + (size_t)r * Ncols + c)       = L0.u;
                *reinterpret_cast<uint32_t*>(Ch + (size_t)(r + 8) * Ncols + c) = H1.u;
                *reinterpret_cast<uint32_t*>(Cl + (size_t)(r + 8) * Ncols + c) = L1.u;
            }
        }
    }
}

// ---------------------------------------------------------------------------
// fp32 -> bf16 hi/lo split (elementwise, vectorized)
// ---------------------------------------------------------------------------
__global__ __launch_bounds__(256)
void split_kernel(const float* __restrict__ in, bf16* __restrict__ oh,
                  bf16* __restrict__ ol, int n4)
{
    const int i = blockIdx.x * 256 + threadIdx.x;
    if (i >= n4) return;
    float4 v = reinterpret_cast<const float4*>(in)[i];
    union { bf16 e[4]; uint2 u; } H, L;
    H.e[0] = __float2bfloat16(v.x); L.e[0] = __float2bfloat16(v.x - __bfloat162float(H.e[0]));
    H.e[1] = __float2bfloat16(v.y); L.e[1] = __float2bfloat16(v.y - __bfloat162float(H.e[1]));
    H.e[2] = __float2bfloat16(v.z); L.e[2] = __float2bfloat16(v.z - __bfloat162float(H.e[2]));
    H.e[3] = __float2bfloat16(v.w); L.e[3] = __float2bfloat16(v.w - __bfloat162float(H.e[3]));
    reinterpret_cast<uint2*>(oh)[i] = H.u;
    reinterpret_cast<uint2*>(ol)[i] = L.u;
}

// in [R,C] fp32 row-major -> out [C,R] bf16 hi/lo (transpose + split)
__global__ __launch_bounds__(256)
void transpose_split_kernel(const float* __restrict__ in, bf16* __restrict__ oh,
                            bf16* __restrict__ ol, int R, int C)
{
    __shared__ float tile[32][33];
    const int c  = blockIdx.x * 32 + threadIdx.x;
    const int r0 = blockIdx.y * 32;
    #pragma unroll
    for (int i = threadIdx.y; i < 32; i += 8)
        tile[i][threadIdx.x] = in[(size_t)(r0 + i) * C + c];
    __syncthreads();
    const int rr = r0 + threadIdx.x;       // output column (= input row)
    const int cc = blockIdx.x * 32;        // output row base (= input col)
    #pragma unroll
    for (int i = threadIdx.y; i < 32; i += 8) {
        float v = tile[threadIdx.x][i];
        bf16 h = __float2bfloat16(v);
        oh[(size_t)(cc + i) * R + rr] = h;
        ol[(size_t)(cc + i) * R + rr] = __float2bfloat16(v - __bfloat162float(h));
    }
}

// ---------------------------------------------------------------------------
// Per-row fusion: s = dot(t_row, zB_row); LN over 4097 virtual features;
// emit normalized x (4096 cols) as bf16 hi/lo planes + normalized s (fp32).
// ---------------------------------------------------------------------------
__global__ __launch_bounds__(256)
void row_fuse_kernel(const float* __restrict__ zA, const float* __restrict__ zB,
                     const float* __restrict__ t,
                     const float* __restrict__ ln_g, const float* __restrict__ ln_b,
                     bf16* __restrict__ xh, bf16* __restrict__ xl,
                     float* __restrict__ sn)
{
    const int n = blockIdx.x;
    const float* a  = zA + (size_t)n * DIM;
    const float* b  = zB + (size_t)n * DIM;
    const float* tt = t  + (size_t)n * DIM;

    float va[4], vb[4], vh[4], vd[4];
    float sp = 0.0f, sum = 0.0f, sq = 0.0f;

    #pragma unroll
    for (int i = 0; i < 4; i++) {
        const int c = threadIdx.x + i * 256;
        float x1 = a[c], x2 = b[c];
        float hd = x1 * x2;
        float df = fabsf(x1 - x2);
        va[i] = x1; vb[i] = x2; vh[i] = hd; vd[i] = df;
        sp  = fmaf(tt[c], x2, sp);
        sum += x1 + x2 + hd + df;
        sq  = fmaf(x1, x1, sq); sq = fmaf(x2, x2, sq);
        sq  = fmaf(hd, hd, sq); sq = fmaf(df, df, sq);
    }

    #pragma unroll
    for (int off = 16; off > 0; off >>= 1) {
        sp  += __shfl_down_sync(0xFFFFFFFFu, sp,  off);
        sum += __shfl_down_sync(0xFFFFFFFFu, sum, off);
        sq  += __shfl_down_sync(0xFFFFFFFFu, sq,  off);
    }
    __shared__ float red[3][8];
    __shared__ float bc[3];
    const int lane = threadIdx.x & 31;
    const int w    = threadIdx.x >> 5;
    if (lane == 0) { red[0][w] = sp; red[1][w] = sum; red[2][w] = sq; }
    __syncthreads();
    if (threadIdx.x == 0) {
        float S = 0, SU = 0, SQ = 0;
        #pragma unroll
        for (int i = 0; i < 8; i++) { S += red[0][i]; SU += red[1][i]; SQ += red[2][i]; }
        bc[0] = S; bc[1] = SU; bc[2] = SQ;
    }
    __syncthreads();

    const float s     = bc[0];
    const float total = bc[1] + s;
    const float totsq = bc[2] + s * s;
    const float inv   = 1.0f / 4097.0f;
    const float mean  = total * inv;
    const float var   = totsq * inv - mean * mean;
    const float rstd  = rsqrtf(var + 1e-5f);

    bf16* xhr = xh + (size_t)n * HIDDEN;
    bf16* xlr = xl + (size_t)n * HIDDEN;
    #pragma unroll
    for (int i = 0; i < 4; i++) {
        const int c = threadIdx.x + i * 256;
        #pragma unroll
        for (int seg = 0; seg < 4; seg++) {
            const int cc = seg * 1024 + c;
            float vsrc = (seg == 0) ? va[i] : (seg == 1) ? vb[i] : (seg == 2) ? vh[i] : vd[i];
            float v = (vsrc - mean) * rstd * ln_g[cc] + ln_b[cc];
            bf16 hb = __float2bfloat16(v);
            xhr[cc] = hb;
            xlr[cc] = __float2bfloat16(v - __bfloat162float(hb));
        }
    }
    if (threadIdx.x == 0)
        sn[n] = (s - mean) * rstd * ln_g[4096] + ln_b[4096];
}

// ---------------------------------------------------------------------------
extern "C" void kernel_launch(void* const* d_in, const int* in_sizes, int n_in,
                              void* d_out, int out_size)
{
    const float* zA   = (const float*)d_in[0];
    const float* zB   = (const float*)d_in[1];
    const float* bil  = (const float*)d_in[2];
    const float* ln_g = (const float*)d_in[3];
    const float* ln_b = (const float*)d_in[4];
    const float* W1   = (const float*)d_in[5];
    const float* b1   = (const float*)d_in[6];
    const float* W2   = (const float*)d_in[7];
    const float* b2   = (const float*)d_in[8];
    float* out = (float*)d_out;

    bf16 *zA_h, *zA_l, *bilT_h, *bilT_l, *w1t_h, *w1t_l, *w2t_h, *w2t_l;
    bf16 *xn_h, *xn_l, *h_h, *h_l;
    float *t, *sn;
    cudaGetSymbolAddress((void**)&zA_h,  g_zA_h);
    cudaGetSymbolAddress((void**)&zA_l,  g_zA_l);
    cudaGetSymbolAddress((void**)&bilT_h, g_bilT_h);
    cudaGetSymbolAddress((void**)&bilT_l, g_bilT_l);
    cudaGetSymbolAddress((void**)&w1t_h, g_w1t_h);
    cudaGetSymbolAddress((void**)&w1t_l, g_w1t_l);
    cudaGetSymbolAddress((void**)&w2t_h, g_w2t_h);
    cudaGetSymbolAddress((void**)&w2t_l, g_w2t_l);
    cudaGetSymbolAddress((void**)&t,     g_t);
    cudaGetSymbolAddress((void**)&xn_h,  g_xn_h);
    cudaGetSymbolAddress((void**)&xn_l,  g_xn_l);
    cudaGetSymbolAddress((void**)&h_h,   g_h_h);
    cudaGetSymbolAddress((void**)&h_l,   g_h_l);
    cudaGetSymbolAddress((void**)&sn,    g_sn);

    cudaFuncSetAttribute(gemm_mma<0>, cudaFuncAttributeMaxDynamicSharedMemorySize, GSM_BYTES);
    cudaFuncSetAttribute(gemm_mma<1>, cudaFuncAttributeMaxDynamicSharedMemorySize, GSM_BYTES);
    cudaFuncSetAttribute(gemm_mma<2>, cudaFuncAttributeMaxDynamicSharedMemorySize, GSM_BYTES);

    // 0) operand conversions
    split_kernel<<<(N_ROWS * DIM / 4 + 255) / 256, 256>>>(zA, zA_h, zA_l, N_ROWS * DIM / 4);
    transpose_split_kernel<<<dim3(DIM / 32, DIM / 32), dim3(32, 8)>>>(bil, bilT_h, bilT_l, DIM, DIM);
    transpose_split_kernel<<<dim3(HIDDEN / 32, HIDDEN / 32), dim3(32, 8)>>>(W1, w1t_h, w1t_l, HIDDEN, HIDDEN);
    transpose_split_kernel<<<dim3(DIM / 32, HIDDEN / 32), dim3(32, 8)>>>(W2, w2t_h, w2t_l, HIDDEN, DIM);

    // 1) t = zA @ bilinear   [16384,1024]
    gemm_mma<0><<<dim3(DIM / 128, N_ROWS / 128), 256, GSM_BYTES>>>(
        zA_h, zA_l, bilT_h, bilT_l, DIM, DIM, t, nullptr, nullptr,
        nullptr, nullptr, nullptr);

    // 2) s + LayerNorm -> xn (bf16 hi/lo), sn
    row_fuse_kernel<<<N_ROWS, 256>>>(zA, zB, t, ln_g, ln_b, xn_h, xn_l, sn);

    // 3) h = gelu(xn @ W1[:4096] + sn*W1[4096,:] + b1)  (bf16 hi/lo out)
    gemm_mma<1><<<dim3(HIDDEN / 128, N_ROWS / 128), 256, GSM_BYTES>>>(
        xn_h, xn_l, w1t_h, w1t_l, HIDDEN, HIDDEN, nullptr, h_h, h_l,
        b1, W1 + (size_t)4096 * HIDDEN, sn);

    // 4) out = gelu(h @ W2 + b2)  (fp32)
    gemm_mma<2><<<dim3(DIM / 128, N_ROWS / 128), 256, GSM_BYTES>>>(
        h_h, h_l, w2t_h, w2t_l, HIDDEN, DIM, out, nullptr, nullptr,
        b2, nullptr, nullptr);
}

// round 5
// speedup vs baseline: 2.7378x; 1.3153x over previous
#include <cuda_runtime.h>
#include <cuda_bf16.h>
#include <math.h>
#include <stdint.h>

#define N_ROWS 16384
#define DIM    1024
#define HIDDEN 4096

typedef __nv_bfloat16 bf16;

// ---------------------------------------------------------------------------
// Scratch (static device globals — allocation-free per harness rules)
// ---------------------------------------------------------------------------
__device__ __align__(128) bf16  g_zA_h [(size_t)N_ROWS * DIM];
__device__ __align__(128) bf16  g_zA_l [(size_t)N_ROWS * DIM];
__device__ __align__(128) bf16  g_bilT_h[(size_t)DIM * DIM];
__device__ __align__(128) bf16  g_bilT_l[(size_t)DIM * DIM];
__device__ __align__(128) bf16  g_w1t_h[(size_t)HIDDEN * HIDDEN];
__device__ __align__(128) bf16  g_w1t_l[(size_t)HIDDEN * HIDDEN];
__device__ __align__(128) bf16  g_w2t_h[(size_t)DIM * HIDDEN];
__device__ __align__(128) bf16  g_w2t_l[(size_t)DIM * HIDDEN];
__device__ __align__(128) float g_t    [(size_t)N_ROWS * DIM];
__device__ __align__(128) bf16  g_xn_h [(size_t)N_ROWS * HIDDEN];
__device__ __align__(128) bf16  g_xn_l [(size_t)N_ROWS * HIDDEN];
__device__ __align__(128) bf16  g_h_h  [(size_t)N_ROWS * HIDDEN];
__device__ __align__(128) bf16  g_h_l  [(size_t)N_ROWS * HIDDEN];
__device__ __align__(128) float g_sn   [N_ROWS];

// ---------------------------------------------------------------------------
// Baseline-PTX helpers (sm_80-era features only: cp.async, ldmatrix, mma.sync)
// ---------------------------------------------------------------------------
__device__ __forceinline__ uint32_t smem_u32(const void* p) {
    uint32_t a;
    asm("{ .reg .u64 t; cvta.to.shared.u64 t, %1; cvt.u32.u64 %0, t; }"
        : "=r"(a) : "l"(p));
    return a;
}

#define CP16(dst, src) \
    asm volatile("cp.async.cg.shared.global [%0], [%1], 16;" \
        :: "r"(dst), "l"(src))
#define CP_COMMIT() asm volatile("cp.async.commit_group;" ::: "memory")
#define CP_WAIT0()  asm volatile("cp.async.wait_group 0;" ::: "memory")

#define LDSM_X4(r, addr) \
    asm volatile("ldmatrix.sync.aligned.m8n8.x4.shared.b16 {%0,%1,%2,%3}, [%4];" \
        : "=r"((r)[0]), "=r"((r)[1]), "=r"((r)[2]), "=r"((r)[3]) : "r"(addr))

__device__ __forceinline__ void mma_bf16(float* d, const uint32_t* a,
                                         uint32_t b0, uint32_t b1) {
    asm volatile(
        "mma.sync.aligned.m16n8k16.row.col.f32.bf16.bf16.f32 "
        "{%0,%1,%2,%3}, {%4,%5,%6,%7}, {%8,%9}, {%0,%1,%2,%3};"
        : "+f"(d[0]), "+f"(d[1]), "+f"(d[2]), "+f"(d[3])
        : "r"(a[0]), "r"(a[1]), "r"(a[2]), "r"(a[3]), "r"(b0), "r"(b1));
}

__device__ __forceinline__ float gelu_exact(float x) {
    return 0.5f * x * (1.0f + erff(x * 0.70710678118654752440f));
}

// ---------------------------------------------------------------------------
// mma.sync GEMM, 3xBF16 split precision.
// D[M,Ncols] = (Ah+Al)[M,K] @ (Bh+Bl)[Ncols,K]^T   (B stored transposed [N,K])
// BM=BN=128, BK=32, 8 warps (2x4), warp tile 64x32.
// 2-stage cp.async pipeline, 2 CTAs/SM, single __syncthreads per chunk.
// SMEM pitch 80B (64B data + 16B pad): bank-group of (row r, chunk c) is
// (5r + c) mod 8 — a complete residue system over any 8 consecutive rows,
// so ldmatrix phases are conflict-free with NO xor swizzle.
// MODE 0: Cf = acc (fp32)
// MODE 1: g = gelu(acc + svec[r]*wlast[c] + bias[c]) -> Ch/Cl bf16 hi/lo split
// MODE 2: Cf = gelu(acc + bias[c])
// ---------------------------------------------------------------------------
#define PLANE_B 10240            // 128 rows * 80B
#define STAGE_B (4 * PLANE_B)    // Ah, Al, Bh, Bl
#define NSTAGE  2
#define GSM_BYTES (NSTAGE * STAGE_B)

__device__ __forceinline__ void load_stage(
    uint32_t sb, int stage,
    const bf16* __restrict__ Ah, const bf16* __restrict__ Al,
    const bf16* __restrict__ Bh, const bf16* __restrict__ Bl,
    int row0, int col0, int k0, int K, int tid)
{
    const uint32_t s0 = sb + stage * STAGE_B;
    #pragma unroll
    for (int j = 0; j < 8; j++) {
        const int ci    = tid + j * 256;
        const int plane = ci >> 9;          // = j>>1 (const per j)
        const int row   = (ci >> 2) & 127;
        const int ch    = ci & 3;
        const size_t go = (size_t)((plane < 2 ? row0 : col0) + row) * K + k0 + ch * 8;
        const bf16* src = (plane == 0) ? Ah + go :
                          (plane == 1) ? Al + go :
                          (plane == 2) ? Bh + go : Bl + go;
        const uint32_t so = s0 + plane * PLANE_B + row * 80 + (ch << 4);
        CP16(so, src);
    }
    CP_COMMIT();
}

template <int MODE>
__global__ __launch_bounds__(256, 2)
void gemm_mma(const bf16* __restrict__ Ah, const bf16* __restrict__ Al,
              const bf16* __restrict__ Bh, const bf16* __restrict__ Bl,
              int K, int Ncols,
              float* __restrict__ Cf, bf16* __restrict__ Ch, bf16* __restrict__ Cl,
              const float* __restrict__ bias, const float* __restrict__ wlast,
              const float* __restrict__ svec)
{
    extern __shared__ __align__(128) char smem[];
    const uint32_t sb = smem_u32(smem);
    const int tid  = threadIdx.x;
    const int lane = tid & 31;
    const int warp = tid >> 5;
    const int wm   = warp & 1;     // 0..1 -> 64-row panel
    const int wn   = warp >> 1;    // 0..3 -> 32-col panel
    const int row0 = blockIdx.y * 128;
    const int col0 = blockIdx.x * 128;

    const int nch = K >> 5;

    load_stage(sb, 0, Ah, Al, Bh, Bl, row0, col0, 0, K, tid);

    float acc[4][4][4];
    #pragma unroll
    for (int a = 0; a < 4; a++)
        #pragma unroll
        for (int b = 0; b < 4; b++)
            #pragma unroll
            for (int c = 0; c < 4; c++) acc[a][b][c] = 0.0f;

    // ldmatrix lane geometry
    const int arow = wm * 64 + (lane & 7) + ((lane >> 3) & 1) * 8;  // M row
    const int ak   = lane >> 4;                                      // k chunk half
    const int brow = wn * 32 + (lane & 7) + ((lane >> 4) & 1) * 8;  // N row
    const int bk   = (lane >> 3) & 1;

    for (int i = 0; i < nch; i++) {
        CP_WAIT0();            // own shard of chunk i arrived
        __syncthreads();       // all shards visible; all warps done with chunk i-1
        if (i + 1 < nch)       // refill the buffer chunk i-1 used; overlap with MMA i
            load_stage(sb, (i + 1) & 1, Ah, Al, Bh, Bl,
                       row0, col0, (i + 1) << 5, K, tid);

        const uint32_t st = sb + (i & 1) * STAGE_B;
        #pragma unroll
        for (int ks = 0; ks < 2; ks++) {
            uint32_t ahf[4][4], alf[4][4];
            #pragma unroll
            for (int mi = 0; mi < 4; mi++) {
                const uint32_t ra = st + (arow + mi * 16) * 80 + ((ks * 2 + ak) << 4);
                LDSM_X4(ahf[mi], ra);
                LDSM_X4(alf[mi], ra + PLANE_B);
            }
            #pragma unroll
            for (int np = 0; np < 2; np++) {
                const uint32_t rb = st + 2 * PLANE_B + (brow + np * 16) * 80 +
                                    ((ks * 2 + bk) << 4);
                uint32_t bhf[4], blf[4];
                LDSM_X4(bhf, rb);
                LDSM_X4(blf, rb + PLANE_B);
                #pragma unroll
                for (int mi = 0; mi < 4; mi++) {
                    mma_bf16(acc[mi][np * 2 + 0], ahf[mi], bhf[0], bhf[1]);
                    mma_bf16(acc[mi][np * 2 + 0], ahf[mi], blf[0], blf[1]);
                    mma_bf16(acc[mi][np * 2 + 0], alf[mi], bhf[0], bhf[1]);
                    mma_bf16(acc[mi][np * 2 + 1], ahf[mi], bhf[2], bhf[3]);
                    mma_bf16(acc[mi][np * 2 + 1], ahf[mi], blf[2], blf[3]);
                    mma_bf16(acc[mi][np * 2 + 1], alf[mi], bhf[2], bhf[3]);
                }
            }
        }
    }

    // Epilogue. acc layout per mma: c0,c1 -> (r, c..c+1); c2,c3 -> (r+8, c..c+1)
    const int r_base = row0 + wm * 64 + (lane >> 2);
    const int c_base = col0 + wn * 32 + (lane & 3) * 2;

    #pragma unroll
    for (int mi = 0; mi < 4; mi++) {
        const int r = r_base + mi * 16;
        float sv0 = 0.0f, sv1 = 0.0f;
        if (MODE == 1) { sv0 = __ldg(svec + r); sv1 = __ldg(svec + r + 8); }
        #pragma unroll
        for (int ni = 0; ni < 4; ni++) {
            const int c = c_base + ni * 8;
            float v0 = acc[mi][ni][0], v1 = acc[mi][ni][1];
            float v2 = acc[mi][ni][2], v3 = acc[mi][ni][3];
            if (MODE == 0) {
                *reinterpret_cast<float2*>(Cf + (size_t)r * Ncols + c)       = make_float2(v0, v1);
                *reinterpret_cast<float2*>(Cf + (size_t)(r + 8) * Ncols + c) = make_float2(v2, v3);
            } else if (MODE == 2) {
                const float bb0 = __ldg(bias + c), bb1 = __ldg(bias + c + 1);
                *reinterpret_cast<float2*>(Cf + (size_t)r * Ncols + c) =
                    make_float2(gelu_exact(v0 + bb0), gelu_exact(v1 + bb1));
                *reinterpret_cast<float2*>(Cf + (size_t)(r + 8) * Ncols + c) =
                    make_float2(gelu_exact(v2 + bb0), gelu_exact(v3 + bb1));
            } else {
                const float bb0 = __ldg(bias + c), bb1 = __ldg(bias + c + 1);
                const float wl0 = __ldg(wlast + c), wl1 = __ldg(wlast + c + 1);
                float g0 = gelu_exact(v0 + sv0 * wl0 + bb0);
                float g1 = gelu_exact(v1 + sv0 * wl1 + bb1);
                float g2 = gelu_exact(v2 + sv1 * wl0 + bb0);
                float g3 = gelu_exact(v3 + sv1 * wl1 + bb1);
                union { bf16 e[2]; uint32_t u; } H0, H1, L0, L1;
                H0.e[0] = __float2bfloat16(g0);
                H0.e[1] = __float2bfloat16(g1);
                L0.e[0] = __float2bfloat16(g0 - __bfloat162float(H0.e[0]));
                L0.e[1] = __float2bfloat16(g1 - __bfloat162float(H0.e[1]));
                H1.e[0] = __float2bfloat16(g2);
                H1.e[1] = __float2bfloat16(g3);
                L1.e[0] = __float2bfloat16(g2 - __bfloat162float(H1.e[0]));
                L1.e[1] = __float2bfloat16(g3 - __bfloat162float(H1.e[1]));
                *reinterpret_cast<uint32_t*>(Ch + (size_t)r * Ncols + c)       = H0.u;
                *reinterpret_cast<uint32_t*>(Cl + (size_t)r * Ncols + c)       = L0.u;
                *reinterpret_cast<uint32_t*>(Ch + (size_t)(r + 8) * Ncols + c) = H1.u;
                *reinterpret_cast<uint32_t*>(Cl + (size_t)(r + 8) * Ncols + c) = L1.u;
            }
        }
    }
}

// ---------------------------------------------------------------------------
// fp32 -> bf16 hi/lo split (elementwise, vectorized)
// ---------------------------------------------------------------------------
__global__ __launch_bounds__(256)
void split_kernel(const float* __restrict__ in, bf16* __restrict__ oh,
                  bf16* __restrict__ ol, int n4)
{
    const int i = blockIdx.x * 256 + threadIdx.x;
    if (i >= n4) return;
    float4 v = reinterpret_cast<const float4*>(in)[i];
    union { bf16 e[4]; uint2 u; } H, L;
    H.e[0] = __float2bfloat16(v.x); L.e[0] = __float2bfloat16(v.x - __bfloat162float(H.e[0]));
    H.e[1] = __float2bfloat16(v.y); L.e[1] = __float2bfloat16(v.y - __bfloat162float(H.e[1]));
    H.e[2] = __float2bfloat16(v.z); L.e[2] = __float2bfloat16(v.z - __bfloat162float(H.e[2]));
    H.e[3] = __float2bfloat16(v.w); L.e[3] = __float2bfloat16(v.w - __bfloat162float(H.e[3]));
    reinterpret_cast<uint2*>(oh)[i] = H.u;
    reinterpret_cast<uint2*>(ol)[i] = L.u;
}

// in [R,C] fp32 row-major -> out [C,R] bf16 hi/lo (transpose + split)
__global__ __launch_bounds__(256)
void transpose_split_kernel(const float* __restrict__ in, bf16* __restrict__ oh,
                            bf16* __restrict__ ol, int R, int C)
{
    __shared__ float tile[32][33];
    const int c  = blockIdx.x * 32 + threadIdx.x;
    const int r0 = blockIdx.y * 32;
    #pragma unroll
    for (int i = threadIdx.y; i < 32; i += 8)
        tile[i][threadIdx.x] = in[(size_t)(r0 + i) * C + c];
    __syncthreads();
    const int rr = r0 + threadIdx.x;       // output column (= input row)
    const int cc = blockIdx.x * 32;        // output row base (= input col)
    #pragma unroll
    for (int i = threadIdx.y; i < 32; i += 8) {
        float v = tile[threadIdx.x][i];
        bf16 h = __float2bfloat16(v);
        oh[(size_t)(cc + i) * R + rr] = h;
        ol[(size_t)(cc + i) * R + rr] = __float2bfloat16(v - __bfloat162float(h));
    }
}

// ---------------------------------------------------------------------------
// Per-row fusion: s = dot(t_row, zB_row); LN over 4097 virtual features;
// emit normalized x (4096 cols) as bf16 hi/lo planes + normalized s (fp32).
// ---------------------------------------------------------------------------
__global__ __launch_bounds__(256)
void row_fuse_kernel(const float* __restrict__ zA, const float* __restrict__ zB,
                     const float* __restrict__ t,
                     const float* __restrict__ ln_g, const float* __restrict__ ln_b,
                     bf16* __restrict__ xh, bf16* __restrict__ xl,
                     float* __restrict__ sn)
{
    const int n = blockIdx.x;
    const float* a  = zA + (size_t)n * DIM;
    const float* b  = zB + (size_t)n * DIM;
    const float* tt = t  + (size_t)n * DIM;

    float va[4], vb[4], vh[4], vd[4];
    float sp = 0.0f, sum = 0.0f, sq = 0.0f;

    #pragma unroll
    for (int i = 0; i < 4; i++) {
        const int c = threadIdx.x + i * 256;
        float x1 = a[c], x2 = b[c];
        float hd = x1 * x2;
        float df = fabsf(x1 - x2);
        va[i] = x1; vb[i] = x2; vh[i] = hd; vd[i] = df;
        sp  = fmaf(tt[c], x2, sp);
        sum += x1 + x2 + hd + df;
        sq  = fmaf(x1, x1, sq); sq = fmaf(x2, x2, sq);
        sq  = fmaf(hd, hd, sq); sq = fmaf(df, df, sq);
    }

    #pragma unroll
    for (int off = 16; off > 0; off >>= 1) {
        sp  += __shfl_down_sync(0xFFFFFFFFu, sp,  off);
        sum += __shfl_down_sync(0xFFFFFFFFu, sum, off);
        sq  += __shfl_down_sync(0xFFFFFFFFu, sq,  off);
    }
    __shared__ float red[3][8];
    __shared__ float bc[3];
    const int lane = threadIdx.x & 31;
    const int w    = threadIdx.x >> 5;
    if (lane == 0) { red[0][w] = sp; red[1][w] = sum; red[2][w] = sq; }
    __syncthreads();
    if (threadIdx.x == 0) {
        float S = 0, SU = 0, SQ = 0;
        #pragma unroll
        for (int i = 0; i < 8; i++) { S += red[0][i]; SU += red[1][i]; SQ += red[2][i]; }
        bc[0] = S; bc[1] = SU; bc[2] = SQ;
    }
    __syncthreads();

    const float s     = bc[0];
    const float total = bc[1] + s;
    const float totsq = bc[2] + s * s;
    const float inv   = 1.0f / 4097.0f;
    const float mean  = total * inv;
    const float var   = totsq * inv - mean * mean;
    const float rstd  = rsqrtf(var + 1e-5f);

    bf16* xhr = xh + (size_t)n * HIDDEN;
    bf16* xlr = xl + (size_t)n * HIDDEN;
    #pragma unroll
    for (int i = 0; i < 4; i++) {
        const int c = threadIdx.x + i * 256;
        #pragma unroll
        for (int seg = 0; seg < 4; seg++) {
            const int cc = seg * 1024 + c;
            float vsrc = (seg == 0) ? va[i] : (seg == 1) ? vb[i] : (seg == 2) ? vh[i] : vd[i];
            float v = (vsrc - mean) * rstd * ln_g[cc] + ln_b[cc];
            bf16 hb = __float2bfloat16(v);
            xhr[cc] = hb;
            xlr[cc] = __float2bfloat16(v - __bfloat162float(hb));
        }
    }
    if (threadIdx.x == 0)
        sn[n] = (s - mean) * rstd * ln_g[4096] + ln_b[4096];
}

// ---------------------------------------------------------------------------
extern "C" void kernel_launch(void* const* d_in, const int* in_sizes, int n_in,
                              void* d_out, int out_size)
{
    const float* zA   = (const float*)d_in[0];
    const float* zB   = (const float*)d_in[1];
    const float* bil  = (const float*)d_in[2];
    const float* ln_g = (const float*)d_in[3];
    const float* ln_b = (const float*)d_in[4];
    const float* W1   = (const float*)d_in[5];
    const float* b1   = (const float*)d_in[6];
    const float* W2   = (const float*)d_in[7];
    const float* b2   = (const float*)d_in[8];
    float* out = (float*)d_out;

    bf16 *zA_h, *zA_l, *bilT_h, *bilT_l, *w1t_h, *w1t_l, *w2t_h, *w2t_l;
    bf16 *xn_h, *xn_l, *h_h, *h_l;
    float *t, *sn;
    cudaGetSymbolAddress((void**)&zA_h,  g_zA_h);
    cudaGetSymbolAddress((void**)&zA_l,  g_zA_l);
    cudaGetSymbolAddress((void**)&bilT_h, g_bilT_h);
    cudaGetSymbolAddress((void**)&bilT_l, g_bilT_l);
    cudaGetSymbolAddress((void**)&w1t_h, g_w1t_h);
    cudaGetSymbolAddress((void**)&w1t_l, g_w1t_l);
    cudaGetSymbolAddress((void**)&w2t_h, g_w2t_h);
    cudaGetSymbolAddress((void**)&w2t_l, g_w2t_l);
    cudaGetSymbolAddress((void**)&t,     g_t);
    cudaGetSymbolAddress((void**)&xn_h,  g_xn_h);
    cudaGetSymbolAddress((void**)&xn_l,  g_xn_l);
    cudaGetSymbolAddress((void**)&h_h,   g_h_h);
    cudaGetSymbolAddress((void**)&h_l,   g_h_l);
    cudaGetSymbolAddress((void**)&sn,    g_sn);

    cudaFuncSetAttribute(gemm_mma<0>, cudaFuncAttributeMaxDynamicSharedMemorySize, GSM_BYTES);
    cudaFuncSetAttribute(gemm_mma<1>, cudaFuncAttributeMaxDynamicSharedMemorySize, GSM_BYTES);
    cudaFuncSetAttribute(gemm_mma<2>, cudaFuncAttributeMaxDynamicSharedMemorySize, GSM_BYTES);

    // 0) operand conversions
    split_kernel<<<(N_ROWS * DIM / 4 + 255) / 256, 256>>>(zA, zA_h, zA_l, N_ROWS * DIM / 4);
    transpose_split_kernel<<<dim3(DIM / 32, DIM / 32), dim3(32, 8)>>>(bil, bilT_h, bilT_l, DIM, DIM);
    transpose_split_kernel<<<dim3(HIDDEN / 32, HIDDEN / 32), dim3(32, 8)>>>(W1, w1t_h, w1t_l, HIDDEN, HIDDEN);
    transpose_split_kernel<<<dim3(DIM / 32, HIDDEN / 32), dim3(32, 8)>>>(W2, w2t_h, w2t_l, HIDDEN, DIM);

    // 1) t = zA @ bilinear   [16384,1024]
    gemm_mma<0><<<dim3(DIM / 128, N_ROWS / 128), 256, GSM_BYTES>>>(
        zA_h, zA_l, bilT_h, bilT_l, DIM, DIM, t, nullptr, nullptr,
        nullptr, nullptr, nullptr);

    // 2) s + LayerNorm -> xn (bf16 hi/lo), sn
    row_fuse_kernel<<<N_ROWS, 256>>>(zA, zB, t, ln_g, ln_b, xn_h, xn_l, sn);

    // 3) h = gelu(xn @ W1[:4096] + sn*W1[4096,:] + b1)  (bf16 hi/lo out)
    gemm_mma<1><<<dim3(HIDDEN / 128, N_ROWS / 128), 256, GSM_BYTES>>>(
        xn_h, xn_l, w1t_h, w1t_l, HIDDEN, HIDDEN, nullptr, h_h, h_l,
        b1, W1 + (size_t)4096 * HIDDEN, sn);

    // 4) out = gelu(h @ W2 + b2)  (fp32)
    gemm_mma<2><<<dim3(DIM / 128, N_ROWS / 128), 256, GSM_BYTES>>>(
        h_h, h_l, w2t_h, w2t_l, HIDDEN, DIM, out, nullptr, nullptr,
        b2, nullptr, nullptr);
}